// round 2
// baseline (speedup 1.0000x reference)
#include <cuda_runtime.h>

// out[b,m] = dot(inputs[b,m,:], W[m,:]) + bias[m]
// B=1024, M=2048, I=128 (fp32)
// HBM-bound: ~1.08 GB traffic per launch. One warp computes ROWS_PER_WARP rows;
// each lane loads one float4 per row (coalesced 512B/row), fmaf dot, butterfly reduce.

constexpr int B_DIM = 1024;
constexpr int M_DIM = 2048;
constexpr int I_DIM = 128;                 // 32 float4 per row
constexpr int ROWS_PER_WARP = 4;
constexpr int THREADS = 256;               // 8 warps/block
constexpr long long TOTAL_ROWS = (long long)B_DIM * M_DIM;   // 2,097,152
constexpr int ROWS_PER_BLOCK = ROWS_PER_WARP * (THREADS / 32); // 32
constexpr int GRID = (int)(TOTAL_ROWS / ROWS_PER_BLOCK);       // 65,536

__global__ __launch_bounds__(THREADS)
void diag_linear_kernel(const float4* __restrict__ x,     // [B*M, 32] float4
                        const float4* __restrict__ w,     // [M, 32] float4
                        const float*  __restrict__ bias,  // [M]
                        float*        __restrict__ out)   // [B*M]
{
    const int lane = threadIdx.x & 31;
    const int warp_in_block = threadIdx.x >> 5;
    const long long warp_global = (long long)blockIdx.x * (THREADS / 32) + warp_in_block;
    const long long row0 = warp_global * ROWS_PER_WARP;

    // Front-batch all global loads for MLP (8 independent LDG.128 in flight).
    float4 a[ROWS_PER_WARP];
    float4 ww[ROWS_PER_WARP];
#pragma unroll
    for (int r = 0; r < ROWS_PER_WARP; r++) {
        a[r] = x[(row0 + r) * (I_DIM / 4) + lane];
    }
#pragma unroll
    for (int r = 0; r < ROWS_PER_WARP; r++) {
        const int m = (int)((row0 + r) & (M_DIM - 1));
        ww[r] = w[(long long)m * (I_DIM / 4) + lane];
    }

#pragma unroll
    for (int r = 0; r < ROWS_PER_WARP; r++) {
        float s = fmaf(a[r].x, ww[r].x,
                  fmaf(a[r].y, ww[r].y,
                  fmaf(a[r].z, ww[r].z,
                       a[r].w * ww[r].w)));
#pragma unroll
        for (int off = 16; off; off >>= 1)
            s += __shfl_xor_sync(0xffffffffu, s, off);

        if (lane == 0) {
            const int m = (int)((row0 + r) & (M_DIM - 1));
            out[row0 + r] = s + __ldg(&bias[m]);
        }
    }
}

extern "C" void kernel_launch(void* const* d_in, const int* in_sizes, int n_in,
                              void* d_out, int out_size)
{
    const float4* x    = (const float4*)d_in[0];  // inputs  [B, M, I]
    const float4* w    = (const float4*)d_in[1];  // Rk_weight [M, I]
    const float*  bias = (const float*)d_in[2];   // bias [M]
    float* out = (float*)d_out;                   // [B, M]

    diag_linear_kernel<<<GRID, THREADS>>>(x, w, bias, out);
}